// round 7
// baseline (speedup 1.0000x reference)
#include <cuda_runtime.h>
#include <cuda_fp16.h>

namespace {
constexpr int H = 128, Wd = 128;
constexpr int PLANE = H * Wd;                       // 16384
constexpr int NPLANES = 32 * 64;                    // 2048
constexpr long long TOTROWS = (long long)NPLANES * H;  // 262144
constexpr int NBLK = 608;                           // ~4 CTAs/SM
constexpr int NWARP = NBLK * 8;                     // 4864 warp strips
}

struct RowS {
    float x[6];   // [0]=left edge, [1..4]=own 4 cols, [5]=right edge
    int   b[6];   // bins
};

__device__ __forceinline__ float4 ldrow(const float* __restrict__ xp, int r,
                                        int lane) {
    float4 v = make_float4(0.f, 0.f, 0.f, 0.f);
    if ((unsigned)r < (unsigned)H)
        v = __ldg(reinterpret_cast<const float4*>(xp + r * Wd + lane * 4));
    return v;
}

__device__ __forceinline__ int quant(float x) {
    return (int)fminf(x * 5.0f, 4.0f);          // x>=0; floor==trunc
}

// Quantize + edge exchange (2 MIO ops; edge bins recomputed on fma pipe).
__device__ __forceinline__ void build(float4 v, int lane, RowS& R) {
    R.x[1] = v.x; R.x[2] = v.y; R.x[3] = v.z; R.x[4] = v.w;
#pragma unroll
    for (int i = 1; i <= 4; ++i) R.b[i] = quant(R.x[i]);
    R.x[0] = __shfl_up_sync(0xffffffffu, v.w, 1);
    R.x[5] = __shfl_down_sync(0xffffffffu, v.x, 1);
    if (lane == 0)  R.x[0] = 0.f;   // x=0 kills the term; b irrelevant
    if (lane == 31) R.x[5] = 0.f;
    R.b[0] = quant(R.x[0]);
    R.b[5] = quant(R.x[5]);
}

__global__ __launch_bounds__(256, 4)
void col_kernel(const float* __restrict__ x,
                const float* __restrict__ Wp,
                const float* __restrict__ Lp,
                float* __restrict__ out) {
    // Pair table (fp16x2): entry idx = rp*125 + bq0*25 + bq1*5 + bp,
    // bank-replicated 32x. One LDS.32 yields WL for (dw=0, dw=1) of row rp.
    // addr = base + lane*4 + bp*128 + bq1*640 + bq0*3200 + rp*16000.
    __shared__ __half2 sP[375 * 32];          // 48000 B

    for (int t = threadIdx.x; t < 375 * 32; t += 256) {
        int idx = t >> 5;
        int rp  = idx / 125;
        int rem = idx - rp * 125;
        int bq0 = rem / 25;  int r2 = rem - bq0 * 25;
        int bq1 = r2 / 5;    int bp = r2 - bq1 * 5;
        float w0 = Wp[rp * 3 + 0] * Lp[bq0 * 5 + bp];
        float w1 = Wp[rp * 3 + 1] * Lp[bq1 * 5 + bp];
        sP[t] = __floats2half2_rn(w0, w1);
    }

    // Register shuffle-tables for the dw=2 singles: lane l (<25) holds
    // W[rp*3+2] * L[l], l = bq*5 + bp.
    const int lane = threadIdx.x & 31;
    float lval = (lane < 25) ? __ldg(Lp + lane) : 0.f;
    const float WLs0 = __ldg(Wp + 2) * lval;
    const float WLs1 = __ldg(Wp + 5) * lval;
    const float WLs2 = __ldg(Wp + 8) * lval;
    __syncthreads();

    const int gw = blockIdx.x * 8 + (threadIdx.x >> 5);
    const char* pairBase = reinterpret_cast<const char*>(sP) + lane * 4;

    // Contiguous global-row strip for this warp.
    long long gs = (long long)gw * TOTROWS / NWARP;
    long long ge = (long long)(gw + 1) * TOTROWS / NWARP;

    long long s = gs;
    while (s < ge) {
        const int p  = (int)(s >> 7);
        const int rs = (int)(s & 127);
        const int re = min(H, rs + (int)(ge - s));     // segment = one plane
        const float* xp = x + (size_t)p * PLANE;
        float* op = out + (size_t)p * PLANE;

        RowS Rr[3];
        float4 wv[3];
        build(ldrow(xp, rs - 1, lane), lane, Rr[0]);
        build(ldrow(xp, rs,     lane), lane, Rr[1]);
        wv[2] = ldrow(xp, rs + 1, lane);

        // 3-row blocks; all rotation indices static.
        for (int k = rs; k < re; k += 3) {
#pragma unroll
            for (int j = 0; j < 3; ++j) {
                const int r = k + j;
                wv[j] = ldrow(xp, r + 2, lane);            // prefetch
                build(wv[(j + 2) % 3], lane, Rr[(j + 2) % 3]);

                const RowS& A  = Rr[j % 3];
                const RowS& Bc = Rr[(j + 1) % 3];
                const RowS& Cn = Rr[(j + 2) % 3];

                float res[4];
#pragma unroll
                for (int i = 0; i < 4; ++i) {
                    const int bp = Bc.b[i + 1];
                    const char* pbP = pairBase + bp * 128;
                    float sacc = 0.f;
#define COL_PAIR(R, rp)                                                        \
                    {                                                          \
                        __half2 pr = *reinterpret_cast<const __half2*>(        \
                            pbP + (R).b[i] * 3200 + (R).b[i + 1] * 640 +       \
                            (rp) * 16000);                                     \
                        float2 w = __half22float2(pr);                         \
                        sacc += w.x * (R).x[i] + w.y * (R).x[i + 1];           \
                    }
                    COL_PAIR(A, 0) COL_PAIR(Bc, 1) COL_PAIR(Cn, 2)
#undef COL_PAIR
                    // dw=2 singles via register shuffle tables
                    sacc += __shfl_sync(0xffffffffu, WLs0,
                                        A.b[i + 2] * 5 + bp)  * A.x[i + 2];
                    sacc += __shfl_sync(0xffffffffu, WLs1,
                                        Bc.b[i + 2] * 5 + bp) * Bc.x[i + 2];
                    sacc += __shfl_sync(0xffffffffu, WLs2,
                                        Cn.b[i + 2] * 5 + bp) * Cn.x[i + 2];
                    res[i] = sacc;
                }

                if (j == 0 || r < re)
                    *reinterpret_cast<float4*>(op + r * Wd + lane * 4) =
                        make_float4(res[0], res[1], res[2], res[3]);
            }
        }
        s += re - rs;
    }
}

extern "C" void kernel_launch(void* const* d_in, const int* in_sizes, int n_in,
                              void* d_out, int out_size) {
    const float* x = nullptr;
    const float* W = nullptr;
    const float* L = nullptr;
    for (int i = 0; i < n_in; ++i) {
        if (in_sizes[i] == 9)       W = (const float*)d_in[i];
        else if (in_sizes[i] == 25) L = (const float*)d_in[i];
        else                        x = (const float*)d_in[i];
    }
    col_kernel<<<NBLK, 256>>>(x, W, L, (float*)d_out);
}